// round 7
// baseline (speedup 1.0000x reference)
#include <cuda_runtime.h>

#define NN   50000
#define EE   500000
#define EMBD 50
#define C1   256
#define C2   50
#define ED   28
#define TE   32

static __device__ float  g_xl[(size_t)NN * C1];
static __device__ float  g_xr[(size_t)NN * C1];
static __device__ float  g_h1[(size_t)NN * C1];
static __device__ float  g_logit[(size_t)EE * 4];
static __device__ float  g_alpha[(size_t)EE * 4];
static __device__ float  g_max[(size_t)5 * NN];
static __device__ float  g_den[(size_t)5 * NN];
static __device__ int    g_off[NN + 1];
static __device__ int    g_cur[NN];
static __device__ int    g_eid[EE];
static __device__ int    g_esrc[EE];
static __device__ int    g_edst[EE];
static __device__ float  g_o2[(size_t)NN * C2];
static __device__ double g_red[4];

__device__ __forceinline__ float lrelu(float v) { return v > 0.f ? v : 0.2f * v; }

__device__ __forceinline__ void atomicMaxF(float* a, float v) {
    if (!(__float_as_uint(v) >> 31)) atomicMax((int*)a, __float_as_int(v));
    else                             atomicMin((unsigned int*)a, __float_as_uint(v));
}

__global__ void k_init() {
    int i = blockIdx.x * blockDim.x + threadIdx.x;
    if (i < 5 * NN) { g_max[i] = __int_as_float(0xFF800000); g_den[i] = 0.f; }
    if (i < NN) g_cur[i] = 0;
    if (i < 4)  g_red[i] = 0.0;
}

__global__ void k_deg(const int* __restrict__ ei) {
    int e = blockIdx.x * blockDim.x + threadIdx.x;
    if (e < EE) atomicAdd(&g_cur[ei[EE + e]], 1);
}

__global__ void k_scan() {
    const int CH = (NN + 1023) / 1024;
    int t = threadIdx.x;
    int lane = t & 31, w = t >> 5;
    int beg = t * CH;
    int end = beg + CH; if (end > NN) end = NN;
    int s = 0;
    for (int i = beg; i < end; i++) s += g_cur[i];
    int incl = s;
#pragma unroll
    for (int off = 1; off < 32; off <<= 1) {
        int y = __shfl_up_sync(0xffffffffu, incl, off);
        if (lane >= off) incl += y;
    }
    __shared__ int ws[32];
    if (lane == 31) ws[w] = incl;
    __syncthreads();
    if (w == 0) {
        int v = ws[lane];
#pragma unroll
        for (int off = 1; off < 32; off <<= 1) {
            int y = __shfl_up_sync(0xffffffffu, v, off);
            if (lane >= off) v += y;
        }
        ws[lane] = v;
    }
    __syncthreads();
    int run = incl - s + (w > 0 ? ws[w - 1] : 0);
    for (int i = beg; i < end; i++) {
        int v = g_cur[i];
        g_off[i] = run;
        g_cur[i] = run;
        run += v;
    }
    if (t == 1023) g_off[NN] = run;
}

__global__ void k_fill(const int* __restrict__ ei) {
    int e = blockIdx.x * blockDim.x + threadIdx.x;
    if (e < EE) {
        int d = ei[EE + e];
        int pos = atomicAdd(&g_cur[d], 1);
        g_eid[pos]  = e;
        g_esrc[pos] = ei[e];
        g_edst[pos] = d;
    }
}

// node transform L1 (xl or xr per launch): weights in smem, float4 FMA
__global__ __launch_bounds__(256) void k_node1(const int* __restrict__ x,
                                               const float* __restrict__ emb,
                                               const float* __restrict__ W,
                                               const float* __restrict__ bvec,
                                               int sel) {
    extern __shared__ float sm[];
    float* s_w = sm;                  // 50*256
    float* s_h = sm + 12800;          // 32*50
    __shared__ int xs[32];
    int t = threadIdx.x;
    int nb = blockIdx.x * 32;
    if (t < 32) xs[t] = (nb + t < NN) ? x[nb + t] : 0;
    for (int i = t; i < 12800 / 4; i += 256)
        ((float4*)s_w)[i] = ((const float4*)W)[i];
    __syncthreads();
    for (int i = t; i < 32 * EMBD; i += 256) {
        int n = i / EMBD, k = i % EMBD;
        s_h[i] = emb[(size_t)xs[n] * EMBD + k];
    }
    __syncthreads();
    int cg = t & 63, g = t >> 6;
    int c0 = cg * 4;
    float4 bv = *(const float4*)&bvec[c0];
    float4 acc[8];
#pragma unroll
    for (int j = 0; j < 8; j++) acc[j] = bv;
    for (int k = 0; k < EMBD; k++) {
        float4 w = *(const float4*)&s_w[k * C1 + c0];
#pragma unroll
        for (int j = 0; j < 8; j++) {
            float h = s_h[(g * 8 + j) * EMBD + k];
            acc[j].x += h * w.x; acc[j].y += h * w.y;
            acc[j].z += h * w.z; acc[j].w += h * w.w;
        }
    }
    float* dst = sel ? g_xr : g_xl;
#pragma unroll
    for (int j = 0; j < 8; j++) {
        int n = nb + g * 8 + j;
        if (n < NN) *(float4*)&dst[(size_t)n * C1 + c0] = acc[j];
    }
}

// edge logits L1 in CSR order: 32 CSR slots/block, vectorized ea inner loop
__global__ __launch_bounds__(256) void k_edge1(const float* __restrict__ ea,
                                               const float* __restrict__ We,
                                               const float* __restrict__ att) {
    extern __shared__ float sm[];
    float* s_we = sm;                 // 7168
    float* s_m  = sm + 7168;          // 8192
    float* s_ea = sm + 15360;         // 896
    __shared__ int s_src[TE], s_dst[TE], s_eid[TE];
    int t  = threadIdx.x;
    int eb = blockIdx.x * TE;
    if (t < TE) {
        s_src[t] = g_esrc[eb + t];
        s_dst[t] = g_edst[eb + t];
        s_eid[t] = g_eid[eb + t];
    }
    for (int i = t; i < ED * C1 / 4; i += 256)
        ((float4*)s_we)[i] = ((const float4*)We)[i];
    __syncthreads();
    for (int i = t; i < TE * ED; i += 256) {
        int e = i / ED, k = i - e * ED;
        s_ea[e * ED + k] = ea[(size_t)s_eid[e] * ED + k];
    }
    for (int i = t; i < TE * C1 / 4; i += 256) {
        int e  = i >> 6;
        int c4 = (i & 63) * 4;
        float4 a = *(const float4*)&g_xl[(size_t)s_src[e] * C1 + c4];
        float4 b = *(const float4*)&g_xr[(size_t)s_dst[e] * C1 + c4];
        a.x += b.x; a.y += b.y; a.z += b.z; a.w += b.w;
        *(float4*)&s_m[e * C1 + c4] = a;
    }
    __syncthreads();
    int cg = t & 63, eq = t >> 6;
    int c0 = cg * 4;
    float4 acc[8];
#pragma unroll
    for (int j = 0; j < 8; j++)
        acc[j] = *(const float4*)&s_m[(eq * 8 + j) * C1 + c0];
#pragma unroll
    for (int k = 0; k < ED; k += 4) {
        float4 w0 = *(const float4*)&s_we[(k + 0) * C1 + c0];
        float4 w1 = *(const float4*)&s_we[(k + 1) * C1 + c0];
        float4 w2 = *(const float4*)&s_we[(k + 2) * C1 + c0];
        float4 w3 = *(const float4*)&s_we[(k + 3) * C1 + c0];
#pragma unroll
        for (int j = 0; j < 8; j++) {
            float4 a = *(const float4*)&s_ea[(eq * 8 + j) * ED + k];
            acc[j].x += a.x * w0.x + a.y * w1.x + a.z * w2.x + a.w * w3.x;
            acc[j].y += a.x * w0.y + a.y * w1.y + a.z * w2.y + a.w * w3.y;
            acc[j].z += a.x * w0.z + a.y * w1.z + a.z * w2.z + a.w * w3.z;
            acc[j].w += a.x * w0.w + a.y * w1.w + a.z * w2.w + a.w * w3.w;
        }
    }
    float a0 = att[c0], a1 = att[c0 + 1], a2 = att[c0 + 2], a3 = att[c0 + 3];
    float part[8];
#pragma unroll
    for (int j = 0; j < 8; j++)
        part[j] = lrelu(acc[j].x) * a0 + lrelu(acc[j].y) * a1 +
                  lrelu(acc[j].z) * a2 + lrelu(acc[j].w) * a3;
#pragma unroll
    for (int off = 8; off; off >>= 1) {
#pragma unroll
        for (int j = 0; j < 8; j++)
            part[j] += __shfl_down_sync(0xffffffffu, part[j], off);
    }
    int lane = t & 31;
    if ((lane & 15) == 0) {
        int h = cg >> 4;
#pragma unroll
        for (int j = 0; j < 8; j++) {
            int e = eq * 8 + j;
            g_logit[(size_t)(eb + e) * 4 + h] = part[j];   // CSR order
            atomicMaxF(&g_max[s_dst[e] * 4 + h], part[j]);
        }
    }
}

// exp + denom: CSR order, no indirection on logits
__global__ void k_ex1() {
    int p = blockIdx.x * blockDim.x + threadIdx.x;
    if (p < EE) {
        int d = g_edst[p];
        float4 lg = *(const float4*)&g_logit[(size_t)p * 4];
        float4 mx = *(const float4*)&g_max[(size_t)d * 4];
        float4 ex;
        ex.x = expf(lg.x - mx.x); ex.y = expf(lg.y - mx.y);
        ex.z = expf(lg.z - mx.z); ex.w = expf(lg.w - mx.w);
        *(float4*)&g_alpha[(size_t)p * 4] = ex;
        atomicAdd(&g_den[d * 4 + 0], ex.x);
        atomicAdd(&g_den[d * 4 + 1], ex.y);
        atomicAdd(&g_den[d * 4 + 2], ex.z);
        atomicAdd(&g_den[d * 4 + 3], ex.w);
    }
}

// aggregation L1 + fused LN stats
__global__ __launch_bounds__(256) void k_agg1(const float* __restrict__ bias) {
    int t = threadIdx.x;
    int n = blockIdx.x * 4 + (t >> 6);
    int t64 = t & 63;
    int c0 = t64 * 4;
    int h  = t64 >> 4;
    int s = g_off[n], en = g_off[n + 1];
    float4 acc = make_float4(0.f, 0.f, 0.f, 0.f);
    int p = s;
    for (; p + 2 <= en; p += 2) {
        int s0 = g_esrc[p], s1 = g_esrc[p + 1];
        float x0 = g_alpha[(size_t)p * 4 + h];
        float x1 = g_alpha[(size_t)(p + 1) * 4 + h];
        float4 v0 = *(const float4*)&g_xl[(size_t)s0 * C1 + c0];
        float4 v1 = *(const float4*)&g_xl[(size_t)s1 * C1 + c0];
        acc.x += x0 * v0.x + x1 * v1.x; acc.y += x0 * v0.y + x1 * v1.y;
        acc.z += x0 * v0.z + x1 * v1.z; acc.w += x0 * v0.w + x1 * v1.w;
    }
    if (p < en) {
        int s0 = g_esrc[p];
        float x0 = g_alpha[(size_t)p * 4 + h];
        float4 v0 = *(const float4*)&g_xl[(size_t)s0 * C1 + c0];
        acc.x += x0 * v0.x; acc.y += x0 * v0.y;
        acc.z += x0 * v0.z; acc.w += x0 * v0.w;
    }
    float inv = 1.f / (g_den[n * 4 + h] + 1e-16f);
    float4 bv = *(const float4*)&bias[c0];
    float4 o;
    o.x = acc.x * inv + bv.x; o.y = acc.y * inv + bv.y;
    o.z = acc.z * inv + bv.z; o.w = acc.w * inv + bv.w;
    *(float4*)&g_h1[(size_t)n * C1 + c0] = o;
    // fused LN stats
    float sv = o.x + o.y + o.z + o.w;
    float qv = o.x * o.x + o.y * o.y + o.z * o.z + o.w * o.w;
#pragma unroll
    for (int off = 16; off; off >>= 1) {
        sv += __shfl_down_sync(0xffffffffu, sv, off);
        qv += __shfl_down_sync(0xffffffffu, qv, off);
    }
    __shared__ double sh[8], qh[8];
    int lane = t & 31, w = t >> 5;
    if (lane == 0) { sh[w] = (double)sv; qh[w] = (double)qv; }
    __syncthreads();
    if (t == 0) {
        double S = 0.0, Q = 0.0;
        for (int i = 0; i < 8; i++) { S += sh[i]; Q += qh[i]; }
        atomicAdd(&g_red[0], S); atomicAdd(&g_red[1], Q);
    }
}

__global__ void k_ln1(const float* __restrict__ w, const float* __restrict__ b) {
    int i = blockIdx.x * blockDim.x + threadIdx.x;
    if (i < NN * C1) {
        double M = (double)NN * C1;
        double mean = g_red[0] / M;
        double var  = g_red[1] / M - mean * mean;
        float f = 1.f / ((float)sqrt(var > 0.0 ? var : 0.0) + 1e-5f);
        int c = i & (C1 - 1);
        float v = (g_h1[i] - (float)mean) * f * w[c] + b[c];
        g_h1[i] = v > 0.f ? v : 0.f;
    }
}

// node transform L2: 256 threads, 16 nodes/block, 4 groups of 64
__global__ __launch_bounds__(256) void k_node2(const float* __restrict__ Wl,
                                               const float* __restrict__ bl,
                                               const float* __restrict__ Wr,
                                               const float* __restrict__ br) {
    __shared__ float hs[16][C1];
    int t = threadIdx.x;
    int nb = blockIdx.x * 16;
    for (int i = t; i < 16 * C1 / 4; i += 256)
        ((float4*)hs)[i] = *(const float4*)&g_h1[(size_t)nb * C1 + (size_t)i * 4];
    __syncthreads();
    int g = t >> 6, c = t & 63;
    bool act = c < C2;
    float accl[4], accr[4];
    float blv = act ? bl[c] : 0.f, brv = act ? br[c] : 0.f;
#pragma unroll
    for (int j = 0; j < 4; j++) { accl[j] = blv; accr[j] = brv; }
    for (int k = 0; k < C1; k += 4) {
        float wl0 = 0, wl1 = 0, wl2 = 0, wl3 = 0, wr0 = 0, wr1 = 0, wr2 = 0, wr3 = 0;
        if (act) {
            wl0 = Wl[k * C2 + c]; wl1 = Wl[(k + 1) * C2 + c];
            wl2 = Wl[(k + 2) * C2 + c]; wl3 = Wl[(k + 3) * C2 + c];
            wr0 = Wr[k * C2 + c]; wr1 = Wr[(k + 1) * C2 + c];
            wr2 = Wr[(k + 2) * C2 + c]; wr3 = Wr[(k + 3) * C2 + c];
        }
#pragma unroll
        for (int j = 0; j < 4; j++) {
            float4 hv = *(const float4*)&hs[g * 4 + j][k];
            accl[j] += hv.x * wl0 + hv.y * wl1 + hv.z * wl2 + hv.w * wl3;
            accr[j] += hv.x * wr0 + hv.y * wr1 + hv.z * wr2 + hv.w * wr3;
        }
    }
    if (act) {
#pragma unroll
        for (int j = 0; j < 4; j++) {
            int n = nb + g * 4 + j;
            g_xl[(size_t)n * C2 + c] = accl[j];
            g_xr[(size_t)n * C2 + c] = accr[j];
        }
    }
}

// edge logits L2 in CSR order, warp per edge
__global__ __launch_bounds__(256) void k_edge2(const float* __restrict__ ea,
                                               const float* __restrict__ We,
                                               const float* __restrict__ att) {
    int lane = threadIdx.x & 31;
    int gw = (blockIdx.x * blockDim.x + threadIdx.x) >> 5;
    int nw = (gridDim.x * blockDim.x) >> 5;
    int c0 = lane * 2;
    bool act = c0 < C2;
    float2 w[ED];
#pragma unroll
    for (int k = 0; k < ED; k++)
        w[k] = act ? *(const float2*)&We[k * C2 + c0] : make_float2(0.f, 0.f);
    float2 a2 = act ? *(const float2*)&att[c0] : make_float2(0.f, 0.f);
    for (int p = gw; p < EE; p += nw) {
        int src = g_esrc[p], dst = g_edst[p], e = g_eid[p];
        float eav = (lane < ED) ? ea[(size_t)e * ED + lane] : 0.f;
        float mx = 0.f, my = 0.f;
        if (act) {
            float2 u = *(const float2*)&g_xl[(size_t)src * C2 + c0];
            float2 v = *(const float2*)&g_xr[(size_t)dst * C2 + c0];
            mx = u.x + v.x; my = u.y + v.y;
        }
#pragma unroll
        for (int k = 0; k < ED; k++) {
            float a = __shfl_sync(0xffffffffu, eav, k);
            mx += a * w[k].x; my += a * w[k].y;
        }
        float pt = lrelu(mx) * a2.x + lrelu(my) * a2.y;
#pragma unroll
        for (int off = 16; off; off >>= 1) pt += __shfl_down_sync(0xffffffffu, pt, off);
        if (lane == 0) {
            g_logit[p] = pt;                 // CSR order
            atomicMaxF(&g_max[4 * NN + dst], pt);
        }
    }
}

__global__ void k_ex2() {
    int p = blockIdx.x * blockDim.x + threadIdx.x;
    if (p < EE) {
        int d = g_edst[p];
        float ex = expf(g_logit[p] - g_max[4 * NN + d]);
        g_alpha[p] = ex;
        atomicAdd(&g_den[4 * NN + d], ex);
    }
}

// aggregation L2 + fused LN stats
__global__ __launch_bounds__(256) void k_agg2(const float* __restrict__ bias) {
    int t = threadIdx.x;
    int n = blockIdx.x * 4 + (t >> 6);
    int t64 = t & 63;
    int s = g_off[n], en = g_off[n + 1];
    bool act = t64 < C2;
    float acc = 0.f;
    for (int p = s; p < en; p++) {
        int src = g_esrc[p];
        float ex = g_alpha[p];
        if (act) acc += ex * g_xl[(size_t)src * C2 + t64];
    }
    float o = 0.f;
    if (act) {
        float inv = 1.f / (g_den[4 * NN + n] + 1e-16f);
        o = acc * inv + bias[t64];
        g_o2[(size_t)n * C2 + t64] = o;
    }
    float sv = o, qv = o * o;
#pragma unroll
    for (int off = 16; off; off >>= 1) {
        sv += __shfl_down_sync(0xffffffffu, sv, off);
        qv += __shfl_down_sync(0xffffffffu, qv, off);
    }
    __shared__ double sh[8], qh[8];
    int lane = t & 31, w = t >> 5;
    if (lane == 0) { sh[w] = (double)sv; qh[w] = (double)qv; }
    __syncthreads();
    if (t == 0) {
        double S = 0.0, Q = 0.0;
        for (int i = 0; i < 8; i++) { S += sh[i]; Q += qh[i]; }
        atomicAdd(&g_red[2], S); atomicAdd(&g_red[3], Q);
    }
}

__global__ void k_ln2(float* __restrict__ out, const float* __restrict__ w,
                      const float* __restrict__ b) {
    int i = blockIdx.x * blockDim.x + threadIdx.x;
    if (i < NN * C2) {
        double M = (double)NN * C2;
        double mean = g_red[2] / M;
        double var  = g_red[3] / M - mean * mean;
        float f = 1.f / ((float)sqrt(var > 0.0 ? var : 0.0) + 1e-5f);
        int c = i % C2;
        out[i] = (g_o2[i] - (float)mean) * f * w[c] + b[c];
    }
}

extern "C" void kernel_launch(void* const* d_in, const int* in_sizes, int n_in,
                              void* d_out, int out_size) {
    const int*   x    = (const int*)d_in[0];
    const int*   ei   = (const int*)d_in[1];
    const float* ea   = (const float*)d_in[2];
    const float* emb  = (const float*)d_in[3];
    const float* Wl1  = (const float*)d_in[4];
    const float* bl1  = (const float*)d_in[5];
    const float* Wr1  = (const float*)d_in[6];
    const float* br1  = (const float*)d_in[7];
    const float* We1  = (const float*)d_in[8];
    const float* att1 = (const float*)d_in[9];
    const float* bias1= (const float*)d_in[10];
    const float* ln1w = (const float*)d_in[11];
    const float* ln1b = (const float*)d_in[12];
    const float* Wl2  = (const float*)d_in[13];
    const float* bl2  = (const float*)d_in[14];
    const float* Wr2  = (const float*)d_in[15];
    const float* br2  = (const float*)d_in[16];
    const float* We2  = (const float*)d_in[17];
    const float* att2 = (const float*)d_in[18];
    const float* bias2= (const float*)d_in[19];
    const float* ln2w = (const float*)d_in[20];
    const float* ln2b = (const float*)d_in[21];
    float* out = (float*)d_out;

    const int node1_smem = (12800 + 32 * EMBD) * 4;       // 57.6 KB
    const int edge1_smem = (7168 + 8192 + 896) * 4;       // 65.0 KB
    cudaFuncSetAttribute(k_node1, cudaFuncAttributeMaxDynamicSharedMemorySize, node1_smem);
    cudaFuncSetAttribute(k_edge1, cudaFuncAttributeMaxDynamicSharedMemorySize, edge1_smem);

    // index-3 launch gets profiled -> k_node1 (second instance)
    k_init<<<(5 * NN + 255) / 256, 256>>>();
    k_node1<<<(NN + 31) / 32, 256, node1_smem>>>(x, emb, Wl1, bl1, 0);
    k_deg<<<(EE + 255) / 256, 256>>>(ei);
    k_node1<<<(NN + 31) / 32, 256, node1_smem>>>(x, emb, Wr1, br1, 1);
    k_scan<<<1, 1024>>>();
    k_fill<<<(EE + 255) / 256, 256>>>(ei);
    k_edge1<<<EE / TE, 256, edge1_smem>>>(ea, We1, att1);
    k_ex1<<<(EE + 255) / 256, 256>>>();
    k_agg1<<<NN / 4, 256>>>(bias1);
    k_ln1<<<(NN * C1 + 255) / 256, 256>>>(ln1w, ln1b);
    k_node2<<<NN / 16, 256>>>(Wl2, bl2, Wr2, br2);
    k_edge2<<<4096, 256>>>(ea, We2, att2);
    k_ex2<<<(EE + 255) / 256, 256>>>();
    k_agg2<<<NN / 4, 256>>>(bias2);
    k_ln2<<<(NN * C2 + 255) / 256, 256>>>(out, ln2w, ln2b);
}

// round 8
// speedup vs baseline: 1.7349x; 1.7349x over previous
#include <cuda_runtime.h>

#define NN   50000
#define EE   500000
#define EMBD 50
#define EMBP 52
#define C1   256
#define C2   50
#define ED   28
#define TE   32

static __device__ float  g_xl[(size_t)NN * C1];
static __device__ float  g_xr[(size_t)NN * C1];
static __device__ float  g_h1[(size_t)NN * C1];
static __device__ float  g_logit[(size_t)EE * 4];
static __device__ float  g_max[(size_t)5 * NN];
static __device__ int    g_off[NN + 1];
static __device__ int    g_cur[NN];
static __device__ int    g_eid[EE];
static __device__ int    g_esrc[EE];
static __device__ int    g_edst[EE];
static __device__ float  g_o2[(size_t)NN * C2];
static __device__ double g_red[4];

__device__ __forceinline__ float lrelu(float v) { return v > 0.f ? v : 0.2f * v; }

__device__ __forceinline__ void atomicMaxF(float* a, float v) {
    if (!(__float_as_uint(v) >> 31)) atomicMax((int*)a, __float_as_int(v));
    else                             atomicMin((unsigned int*)a, __float_as_uint(v));
}

__global__ void k_init() {
    int i = blockIdx.x * blockDim.x + threadIdx.x;
    if (i < 5 * NN) g_max[i] = __int_as_float(0xFF800000);
    if (i < NN) g_cur[i] = 0;
    if (i < 4)  g_red[i] = 0.0;
}

__global__ void k_deg(const int* __restrict__ ei) {
    int e = blockIdx.x * blockDim.x + threadIdx.x;
    if (e < EE) atomicAdd(&g_cur[ei[EE + e]], 1);
}

// coalesced single-block scan through 200KB smem
__global__ void k_scan() {
    extern __shared__ int si[];                 // NN ints
    int t = threadIdx.x;
    for (int i = t; i < NN; i += 1024) si[i] = g_cur[i];
    __syncthreads();
    const int CH = (NN + 1023) / 1024;          // 49
    int lane = t & 31, w = t >> 5;
    int beg = t * CH;
    int end = beg + CH; if (end > NN) end = NN;
    int s = 0;
    for (int i = beg; i < end; i++) s += si[i];
    int incl = s;
#pragma unroll
    for (int off = 1; off < 32; off <<= 1) {
        int y = __shfl_up_sync(0xffffffffu, incl, off);
        if (lane >= off) incl += y;
    }
    __shared__ int ws[32];
    if (lane == 31) ws[w] = incl;
    __syncthreads();
    if (w == 0) {
        int v = ws[lane];
#pragma unroll
        for (int off = 1; off < 32; off <<= 1) {
            int y = __shfl_up_sync(0xffffffffu, v, off);
            if (lane >= off) v += y;
        }
        ws[lane] = v;
    }
    __syncthreads();
    int run = incl - s + (w > 0 ? ws[w - 1] : 0);
    for (int i = beg; i < end; i++) {
        int v = si[i];
        si[i] = run;
        run += v;
    }
    __syncthreads();
    for (int i = t; i < NN; i += 1024) {
        int v = si[i];
        g_off[i] = v;
        g_cur[i] = v;
    }
    if (t == 0) g_off[NN] = ws[31];
}

__global__ void k_fill(const int* __restrict__ ei) {
    int e = blockIdx.x * blockDim.x + threadIdx.x;
    if (e < EE) {
        int d = ei[EE + e];
        int pos = atomicAdd(&g_cur[d], 1);
        g_eid[pos]  = e;
        g_esrc[pos] = ei[e];
        g_edst[pos] = d;
    }
}

// node transform L1 (xl or xr per launch): padded K, float4-vectorized inner loop
__global__ __launch_bounds__(256) void k_node1(const int* __restrict__ x,
                                               const float* __restrict__ emb,
                                               const float* __restrict__ W,
                                               const float* __restrict__ bvec,
                                               int sel) {
    extern __shared__ float sm[];
    float* s_w = sm;                  // EMBP*256
    float* s_h = sm + EMBP * C1;      // 32*EMBP
    __shared__ int xs[32];
    int t = threadIdx.x;
    int nb = blockIdx.x * 32;
    if (t < 32) xs[t] = (nb + t < NN) ? x[nb + t] : 0;
    for (int i = t; i < EMBD * C1 / 4; i += 256)
        ((float4*)s_w)[i] = ((const float4*)W)[i];
    for (int i = t; i < (EMBP - EMBD) * C1 / 4; i += 256)
        ((float4*)s_w)[EMBD * C1 / 4 + i] = make_float4(0.f, 0.f, 0.f, 0.f);
    __syncthreads();
    for (int i = t; i < 32 * EMBP; i += 256) {
        int n = i / EMBP, k = i % EMBP;
        s_h[i] = (k < EMBD) ? emb[(size_t)xs[n] * EMBD + k] : 0.f;
    }
    __syncthreads();
    int cg = t & 63, g = t >> 6;
    int c0 = cg * 4;
    float4 bv = *(const float4*)&bvec[c0];
    float4 acc[8];
#pragma unroll
    for (int j = 0; j < 8; j++) acc[j] = bv;
#pragma unroll
    for (int k = 0; k < EMBP; k += 4) {
        float4 w0 = *(const float4*)&s_w[(k + 0) * C1 + c0];
        float4 w1 = *(const float4*)&s_w[(k + 1) * C1 + c0];
        float4 w2 = *(const float4*)&s_w[(k + 2) * C1 + c0];
        float4 w3 = *(const float4*)&s_w[(k + 3) * C1 + c0];
#pragma unroll
        for (int j = 0; j < 8; j++) {
            float4 h4 = *(const float4*)&s_h[(g * 8 + j) * EMBP + k];
            acc[j].x += h4.x * w0.x + h4.y * w1.x + h4.z * w2.x + h4.w * w3.x;
            acc[j].y += h4.x * w0.y + h4.y * w1.y + h4.z * w2.y + h4.w * w3.y;
            acc[j].z += h4.x * w0.z + h4.y * w1.z + h4.z * w2.z + h4.w * w3.z;
            acc[j].w += h4.x * w0.w + h4.y * w1.w + h4.z * w2.w + h4.w * w3.w;
        }
    }
    float* dst = sel ? g_xr : g_xl;
#pragma unroll
    for (int j = 0; j < 8; j++) {
        int n = nb + g * 8 + j;
        if (n < NN) *(float4*)&dst[(size_t)n * C1 + c0] = acc[j];
    }
}

// edge logits L1, CSR order: direct global acc init, vectorized ea inner loop
__global__ __launch_bounds__(256) void k_edge1(const float* __restrict__ ea,
                                               const float* __restrict__ We,
                                               const float* __restrict__ att) {
    extern __shared__ float sm[];
    float* s_we = sm;                 // 28*256 = 7168 floats
    float* s_ea = sm + 7168;          // 32*28 = 896 floats
    __shared__ int s_src[TE], s_dst[TE], s_eid[TE];
    int t  = threadIdx.x;
    int eb = blockIdx.x * TE;
    if (t < TE) {
        s_src[t] = g_esrc[eb + t];
        s_dst[t] = g_edst[eb + t];
        s_eid[t] = g_eid[eb + t];
    }
    for (int i = t; i < ED * C1 / 4; i += 256)
        ((float4*)s_we)[i] = ((const float4*)We)[i];
    __syncthreads();
    for (int i = t; i < TE * ED; i += 256) {
        int e = i / ED, k = i - e * ED;
        s_ea[e * ED + k] = ea[(size_t)s_eid[e] * ED + k];
    }
    int cg = t & 63, eq = t >> 6;
    int c0 = cg * 4;
    float4 acc[8];
#pragma unroll
    for (int j = 0; j < 8; j++) {
        int e = eq * 8 + j;
        float4 a = *(const float4*)&g_xl[(size_t)s_src[e] * C1 + c0];
        float4 b = *(const float4*)&g_xr[(size_t)s_dst[e] * C1 + c0];
        acc[j].x = a.x + b.x; acc[j].y = a.y + b.y;
        acc[j].z = a.z + b.z; acc[j].w = a.w + b.w;
    }
    __syncthreads();
#pragma unroll
    for (int k = 0; k < ED; k += 4) {
        float4 w0 = *(const float4*)&s_we[(k + 0) * C1 + c0];
        float4 w1 = *(const float4*)&s_we[(k + 1) * C1 + c0];
        float4 w2 = *(const float4*)&s_we[(k + 2) * C1 + c0];
        float4 w3 = *(const float4*)&s_we[(k + 3) * C1 + c0];
#pragma unroll
        for (int j = 0; j < 8; j++) {
            float4 a = *(const float4*)&s_ea[(eq * 8 + j) * ED + k];
            acc[j].x += a.x * w0.x + a.y * w1.x + a.z * w2.x + a.w * w3.x;
            acc[j].y += a.x * w0.y + a.y * w1.y + a.z * w2.y + a.w * w3.y;
            acc[j].z += a.x * w0.z + a.y * w1.z + a.z * w2.z + a.w * w3.z;
            acc[j].w += a.x * w0.w + a.y * w1.w + a.z * w2.w + a.w * w3.w;
        }
    }
    float a0 = att[c0], a1 = att[c0 + 1], a2 = att[c0 + 2], a3 = att[c0 + 3];
    float part[8];
#pragma unroll
    for (int j = 0; j < 8; j++)
        part[j] = lrelu(acc[j].x) * a0 + lrelu(acc[j].y) * a1 +
                  lrelu(acc[j].z) * a2 + lrelu(acc[j].w) * a3;
#pragma unroll
    for (int off = 8; off; off >>= 1) {
#pragma unroll
        for (int j = 0; j < 8; j++)
            part[j] += __shfl_down_sync(0xffffffffu, part[j], off);
    }
    int lane = t & 31;
    if ((lane & 15) == 0) {
        int h = cg >> 4;
#pragma unroll
        for (int j = 0; j < 8; j++) {
            int e = eq * 8 + j;
            g_logit[(size_t)(eb + e) * 4 + h] = part[j];   // CSR order
            atomicMaxF(&g_max[s_dst[e] * 4 + h], part[j]);
        }
    }
}

// aggregation L1 with fused softmax (exp+den in-kernel) + fused LN stats
__global__ __launch_bounds__(256) void k_agg1(const float* __restrict__ bias) {
    int t = threadIdx.x;
    int n = blockIdx.x * 4 + (t >> 6);
    int t64 = t & 63;
    int lane = t & 31;
    int c0 = t64 * 4;
    int h  = t64 >> 4;
    int s = g_off[n], en = g_off[n + 1];
    float mx = g_max[n * 4 + h];
    float den = 0.f;
    float4 acc = make_float4(0.f, 0.f, 0.f, 0.f);
    for (int p = s; p < en; p++) {
        float ex = 0.f;
        if ((lane & 15) == 0) ex = expf(g_logit[(size_t)p * 4 + h] - mx);
        ex = __shfl_sync(0xffffffffu, ex, lane & 16);
        den += ex;
        int src = g_esrc[p];
        float4 v = *(const float4*)&g_xl[(size_t)src * C1 + c0];
        acc.x += ex * v.x; acc.y += ex * v.y;
        acc.z += ex * v.z; acc.w += ex * v.w;
    }
    float inv = 1.f / (den + 1e-16f);
    float4 bv = *(const float4*)&bias[c0];
    float4 o;
    o.x = acc.x * inv + bv.x; o.y = acc.y * inv + bv.y;
    o.z = acc.z * inv + bv.z; o.w = acc.w * inv + bv.w;
    *(float4*)&g_h1[(size_t)n * C1 + c0] = o;
    // fused LN stats
    float sv = o.x + o.y + o.z + o.w;
    float qv = o.x * o.x + o.y * o.y + o.z * o.z + o.w * o.w;
#pragma unroll
    for (int off = 16; off; off >>= 1) {
        sv += __shfl_down_sync(0xffffffffu, sv, off);
        qv += __shfl_down_sync(0xffffffffu, qv, off);
    }
    __shared__ double sh[8], qh[8];
    int w = t >> 5;
    if (lane == 0) { sh[w] = (double)sv; qh[w] = (double)qv; }
    __syncthreads();
    if (t == 0) {
        double S = 0.0, Q = 0.0;
        for (int i = 0; i < 8; i++) { S += sh[i]; Q += qh[i]; }
        atomicAdd(&g_red[0], S); atomicAdd(&g_red[1], Q);
    }
}

// node transform L2 with fused LN1 + ReLU on load
__global__ __launch_bounds__(256) void k_node2(const float* __restrict__ Wl,
                                               const float* __restrict__ bl,
                                               const float* __restrict__ Wr,
                                               const float* __restrict__ br,
                                               const float* __restrict__ lnw,
                                               const float* __restrict__ lnb) {
    __shared__ float hs[16][C1];
    __shared__ float s_lnw[C1], s_lnb[C1];
    __shared__ float s_mf[2];
    int t = threadIdx.x;
    int nb = blockIdx.x * 16;
    if (t < C1) { s_lnw[t] = lnw[t]; s_lnb[t] = lnb[t]; }
    if (t == 0) {
        double M = (double)NN * C1;
        double mean = g_red[0] / M;
        double var  = g_red[1] / M - mean * mean;
        s_mf[0] = (float)mean;
        s_mf[1] = 1.f / ((float)sqrt(var > 0.0 ? var : 0.0) + 1e-5f);
    }
    __syncthreads();
    float mean = s_mf[0], f = s_mf[1];
    for (int i = t; i < 16 * C1 / 4; i += 256) {
        float4 v = *(const float4*)&g_h1[(size_t)nb * C1 + (size_t)i * 4];
        int k = (i & 63) * 4;
        float4 w4 = *(const float4*)&s_lnw[k];
        float4 b4 = *(const float4*)&s_lnb[k];
        v.x = (v.x - mean) * f * w4.x + b4.x; v.x = v.x > 0.f ? v.x : 0.f;
        v.y = (v.y - mean) * f * w4.y + b4.y; v.y = v.y > 0.f ? v.y : 0.f;
        v.z = (v.z - mean) * f * w4.z + b4.z; v.z = v.z > 0.f ? v.z : 0.f;
        v.w = (v.w - mean) * f * w4.w + b4.w; v.w = v.w > 0.f ? v.w : 0.f;
        *(float4*)&hs[0][i * 4] = v;
    }
    __syncthreads();
    int g = t >> 6, c = t & 63;
    bool act = c < C2;
    float accl[4], accr[4];
    float blv = act ? bl[c] : 0.f, brv = act ? br[c] : 0.f;
#pragma unroll
    for (int j = 0; j < 4; j++) { accl[j] = blv; accr[j] = brv; }
    for (int k = 0; k < C1; k += 4) {
        float wl0 = 0, wl1 = 0, wl2 = 0, wl3 = 0, wr0 = 0, wr1 = 0, wr2 = 0, wr3 = 0;
        if (act) {
            wl0 = Wl[k * C2 + c]; wl1 = Wl[(k + 1) * C2 + c];
            wl2 = Wl[(k + 2) * C2 + c]; wl3 = Wl[(k + 3) * C2 + c];
            wr0 = Wr[k * C2 + c]; wr1 = Wr[(k + 1) * C2 + c];
            wr2 = Wr[(k + 2) * C2 + c]; wr3 = Wr[(k + 3) * C2 + c];
        }
#pragma unroll
        for (int j = 0; j < 4; j++) {
            float4 hv = *(const float4*)&hs[g * 4 + j][k];
            accl[j] += hv.x * wl0 + hv.y * wl1 + hv.z * wl2 + hv.w * wl3;
            accr[j] += hv.x * wr0 + hv.y * wr1 + hv.z * wr2 + hv.w * wr3;
        }
    }
    if (act) {
#pragma unroll
        for (int j = 0; j < 4; j++) {
            int n = nb + g * 4 + j;
            g_xl[(size_t)n * C2 + c] = accl[j];
            g_xr[(size_t)n * C2 + c] = accr[j];
        }
    }
}

// edge logits L2 in CSR order, warp per edge
__global__ __launch_bounds__(256) void k_edge2(const float* __restrict__ ea,
                                               const float* __restrict__ We,
                                               const float* __restrict__ att) {
    int lane = threadIdx.x & 31;
    int gw = (blockIdx.x * blockDim.x + threadIdx.x) >> 5;
    int nw = (gridDim.x * blockDim.x) >> 5;
    int c0 = lane * 2;
    bool act = c0 < C2;
    float2 w[ED];
#pragma unroll
    for (int k = 0; k < ED; k++)
        w[k] = act ? *(const float2*)&We[k * C2 + c0] : make_float2(0.f, 0.f);
    float2 a2 = act ? *(const float2*)&att[c0] : make_float2(0.f, 0.f);
    for (int p = gw; p < EE; p += nw) {
        int src = g_esrc[p], dst = g_edst[p], e = g_eid[p];
        float eav = (lane < ED) ? ea[(size_t)e * ED + lane] : 0.f;
        float mx = 0.f, my = 0.f;
        if (act) {
            float2 u = *(const float2*)&g_xl[(size_t)src * C2 + c0];
            float2 v = *(const float2*)&g_xr[(size_t)dst * C2 + c0];
            mx = u.x + v.x; my = u.y + v.y;
        }
#pragma unroll
        for (int k = 0; k < ED; k++) {
            float a = __shfl_sync(0xffffffffu, eav, k);
            mx += a * w[k].x; my += a * w[k].y;
        }
        float pt = lrelu(mx) * a2.x + lrelu(my) * a2.y;
#pragma unroll
        for (int off = 16; off; off >>= 1) pt += __shfl_down_sync(0xffffffffu, pt, off);
        if (lane == 0) {
            g_logit[p] = pt;                 // CSR order
            atomicMaxF(&g_max[4 * NN + dst], pt);
        }
    }
}

// aggregation L2 with fused softmax + fused LN stats
__global__ __launch_bounds__(256) void k_agg2(const float* __restrict__ bias) {
    int t = threadIdx.x;
    int n = blockIdx.x * 4 + (t >> 6);
    int t64 = t & 63;
    int lane = t & 31;
    int s = g_off[n], en = g_off[n + 1];
    bool act = t64 < C2;
    float mx = g_max[4 * NN + n];
    float den = 0.f, acc = 0.f;
    for (int p = s; p < en; p++) {
        float ex = 0.f;
        if (lane == 0) ex = expf(g_logit[p] - mx);
        ex = __shfl_sync(0xffffffffu, ex, 0);
        den += ex;
        int src = g_esrc[p];
        if (act) acc += ex * g_xl[(size_t)src * C2 + t64];
    }
    float o = 0.f;
    if (act) {
        o = acc / (den + 1e-16f) + bias[t64];
        g_o2[(size_t)n * C2 + t64] = o;
    }
    float sv = o, qv = o * o;
#pragma unroll
    for (int off = 16; off; off >>= 1) {
        sv += __shfl_down_sync(0xffffffffu, sv, off);
        qv += __shfl_down_sync(0xffffffffu, qv, off);
    }
    __shared__ double sh[8], qh[8];
    int w = t >> 5;
    if (lane == 0) { sh[w] = (double)sv; qh[w] = (double)qv; }
    __syncthreads();
    if (t == 0) {
        double S = 0.0, Q = 0.0;
        for (int i = 0; i < 8; i++) { S += sh[i]; Q += qh[i]; }
        atomicAdd(&g_red[2], S); atomicAdd(&g_red[3], Q);
    }
}

__global__ void k_ln2(float* __restrict__ out, const float* __restrict__ w,
                      const float* __restrict__ b) {
    int i = blockIdx.x * blockDim.x + threadIdx.x;
    if (i < NN * C2) {
        double M = (double)NN * C2;
        double mean = g_red[2] / M;
        double var  = g_red[3] / M - mean * mean;
        float f = 1.f / ((float)sqrt(var > 0.0 ? var : 0.0) + 1e-5f);
        int c = i % C2;
        out[i] = (g_o2[i] - (float)mean) * f * w[c] + b[c];
    }
}

extern "C" void kernel_launch(void* const* d_in, const int* in_sizes, int n_in,
                              void* d_out, int out_size) {
    const int*   x    = (const int*)d_in[0];
    const int*   ei   = (const int*)d_in[1];
    const float* ea   = (const float*)d_in[2];
    const float* emb  = (const float*)d_in[3];
    const float* Wl1  = (const float*)d_in[4];
    const float* bl1  = (const float*)d_in[5];
    const float* Wr1  = (const float*)d_in[6];
    const float* br1  = (const float*)d_in[7];
    const float* We1  = (const float*)d_in[8];
    const float* att1 = (const float*)d_in[9];
    const float* bias1= (const float*)d_in[10];
    const float* ln1w = (const float*)d_in[11];
    const float* ln1b = (const float*)d_in[12];
    const float* Wl2  = (const float*)d_in[13];
    const float* bl2  = (const float*)d_in[14];
    const float* Wr2  = (const float*)d_in[15];
    const float* br2  = (const float*)d_in[16];
    const float* We2  = (const float*)d_in[17];
    const float* att2 = (const float*)d_in[18];
    const float* bias2= (const float*)d_in[19];
    const float* ln2w = (const float*)d_in[20];
    const float* ln2b = (const float*)d_in[21];
    float* out = (float*)d_out;

    const int node1_smem = (EMBP * C1 + 32 * EMBP) * 4;   // ~59.9 KB
    const int edge1_smem = (7168 + 896) * 4;              // ~32.3 KB
    const int scan_smem  = NN * 4;                        // 200 KB
    cudaFuncSetAttribute(k_node1, cudaFuncAttributeMaxDynamicSharedMemorySize, node1_smem);
    cudaFuncSetAttribute(k_edge1, cudaFuncAttributeMaxDynamicSharedMemorySize, edge1_smem);
    cudaFuncSetAttribute(k_scan,  cudaFuncAttributeMaxDynamicSharedMemorySize, scan_smem);

    k_init<<<(5 * NN + 255) / 256, 256>>>();                               // 1
    k_node1<<<(NN + 31) / 32, 256, node1_smem>>>(x, emb, Wl1, bl1, 0);     // 2
    k_deg<<<(EE + 255) / 256, 256>>>(ei);                                  // 3
    k_scan<<<1, 1024, scan_smem>>>();                                      // 4 <- profiled
    k_node1<<<(NN + 31) / 32, 256, node1_smem>>>(x, emb, Wr1, br1, 1);     // 5
    k_fill<<<(EE + 255) / 256, 256>>>(ei);                                 // 6
    k_edge1<<<EE / TE, 256, edge1_smem>>>(ea, We1, att1);                  // 7
    k_agg1<<<NN / 4, 256>>>(bias1);                                        // 8
    k_node2<<<NN / 16, 256>>>(Wl2, bl2, Wr2, br2, ln1w, ln1b);             // 9
    k_edge2<<<4096, 256>>>(ea, We2, att2);                                 // 10
    k_agg2<<<NN / 4, 256>>>(bias2);                                        // 11
    k_ln2<<<(NN * C2 + 255) / 256, 256>>>(out, ln2w, ln2b);                // 12
}

// round 9
// speedup vs baseline: 1.7354x; 1.0003x over previous
#include <cuda_runtime.h>

#define NN   50000
#define EE   500000
#define EMBD 50
#define EMBP 52
#define C1   256
#define C2   50
#define ED   28
#define TE   32

static __device__ float  g_xl[(size_t)NN * C1];
static __device__ float  g_xr[(size_t)NN * C1];
static __device__ float  g_h1[(size_t)NN * C1];
static __device__ float  g_logit[(size_t)EE * 4];
static __device__ float  g_max[(size_t)5 * NN];
static __device__ int    g_off[NN + 1];
static __device__ int    g_cur[NN];
static __device__ int    g_eid[EE];
static __device__ int    g_esrc[EE];
static __device__ int    g_edst[EE];
static __device__ float  g_o2[(size_t)NN * C2];
static __device__ double g_red[4];

__device__ __forceinline__ float lrelu(float v) { return v > 0.f ? v : 0.2f * v; }

__device__ __forceinline__ void atomicMaxF(float* a, float v) {
    if (!(__float_as_uint(v) >> 31)) atomicMax((int*)a, __float_as_int(v));
    else                             atomicMin((unsigned int*)a, __float_as_uint(v));
}

// ---- packed f32x2 helpers ----
__device__ __forceinline__ unsigned long long fma2(unsigned long long a,
                                                   unsigned long long b,
                                                   unsigned long long c) {
    unsigned long long d;
    asm("fma.rn.f32x2 %0, %1, %2, %3;" : "=l"(d) : "l"(a), "l"(b), "l"(c));
    return d;
}
__device__ __forceinline__ unsigned long long pack2(float x, float y) {
    unsigned long long d;
    asm("mov.b64 %0, {%1, %2};" : "=l"(d) : "r"(__float_as_int(x)), "r"(__float_as_int(y)));
    return d;
}
__device__ __forceinline__ float2 unpack2(unsigned long long v) {
    int lo, hi;
    asm("mov.b64 {%0, %1}, %2;" : "=r"(lo), "=r"(hi) : "l"(v));
    return make_float2(__int_as_float(lo), __int_as_float(hi));
}

__global__ void k_init() {
    int i = blockIdx.x * blockDim.x + threadIdx.x;
    if (i < 5 * NN) g_max[i] = __int_as_float(0xFF800000);
    if (i < NN) g_cur[i] = 0;
    if (i < 4)  g_red[i] = 0.0;
}

__global__ void k_deg(const int* __restrict__ ei) {
    int e = blockIdx.x * blockDim.x + threadIdx.x;
    if (e < EE) atomicAdd(&g_cur[ei[EE + e]], 1);
}

// coalesced single-block scan through 200KB smem
__global__ void k_scan() {
    extern __shared__ int si[];
    int t = threadIdx.x;
    for (int i = t; i < NN; i += 1024) si[i] = g_cur[i];
    __syncthreads();
    const int CH = (NN + 1023) / 1024;
    int lane = t & 31, w = t >> 5;
    int beg = t * CH;
    int end = beg + CH; if (end > NN) end = NN;
    int s = 0;
    for (int i = beg; i < end; i++) s += si[i];
    int incl = s;
#pragma unroll
    for (int off = 1; off < 32; off <<= 1) {
        int y = __shfl_up_sync(0xffffffffu, incl, off);
        if (lane >= off) incl += y;
    }
    __shared__ int ws[32];
    if (lane == 31) ws[w] = incl;
    __syncthreads();
    if (w == 0) {
        int v = ws[lane];
#pragma unroll
        for (int off = 1; off < 32; off <<= 1) {
            int y = __shfl_up_sync(0xffffffffu, v, off);
            if (lane >= off) v += y;
        }
        ws[lane] = v;
    }
    __syncthreads();
    int run = incl - s + (w > 0 ? ws[w - 1] : 0);
    for (int i = beg; i < end; i++) {
        int v = si[i];
        si[i] = run;
        run += v;
    }
    __syncthreads();
    for (int i = t; i < NN; i += 1024) {
        int v = si[i];
        g_off[i] = v;
        g_cur[i] = v;
    }
    if (t == 0) g_off[NN] = ws[31];
}

__global__ void k_fill(const int* __restrict__ ei) {
    int e = blockIdx.x * blockDim.x + threadIdx.x;
    if (e < EE) {
        int d = ei[EE + e];
        int pos = atomicAdd(&g_cur[d], 1);
        g_eid[pos]  = e;
        g_esrc[pos] = ei[e];
        g_edst[pos] = d;
    }
}

// node transform L1 (xl or xr per launch): f32x2 with smem-duplicated h splats
__global__ __launch_bounds__(256) void k_node1(const int* __restrict__ x,
                                               const float* __restrict__ emb,
                                               const float* __restrict__ W,
                                               const float* __restrict__ bvec,
                                               int sel) {
    extern __shared__ float sm[];
    float* s_w  = sm;                       // EMBP*C1 = 13312 floats
    float* s_h2 = sm + EMBP * C1;           // 32*EMBP*2 = 3328 floats
    __shared__ int xs[32];
    int t = threadIdx.x;
    int nb = blockIdx.x * 32;
    if (t < 32) xs[t] = (nb + t < NN) ? x[nb + t] : 0;
    for (int i = t; i < EMBD * C1 / 4; i += 256)
        ((float4*)s_w)[i] = ((const float4*)W)[i];
    for (int i = t; i < (EMBP - EMBD) * C1 / 4; i += 256)
        ((float4*)s_w)[EMBD * C1 / 4 + i] = make_float4(0.f, 0.f, 0.f, 0.f);
    __syncthreads();
    for (int i = t; i < 32 * EMBP; i += 256) {
        int n = i / EMBP, k = i % EMBP;
        float v = (k < EMBD) ? emb[(size_t)xs[n] * EMBD + k] : 0.f;
        s_h2[i * 2] = v; s_h2[i * 2 + 1] = v;
    }
    __syncthreads();
    int cg = t & 63, g = t >> 6;
    int c0 = cg * 4;
    float4 bv = *(const float4*)&bvec[c0];
    ulonglong2 acc[8];
#pragma unroll
    for (int j = 0; j < 8; j++) {
        acc[j].x = pack2(bv.x, bv.y);
        acc[j].y = pack2(bv.z, bv.w);
    }
#pragma unroll 4
    for (int k = 0; k < EMBP; k++) {
        ulonglong2 w = *(const ulonglong2*)&s_w[k * C1 + c0];
#pragma unroll
        for (int j = 0; j < 8; j++) {
            unsigned long long h2 =
                *(const unsigned long long*)&s_h2[((g * 8 + j) * EMBP + k) * 2];
            acc[j].x = fma2(h2, w.x, acc[j].x);
            acc[j].y = fma2(h2, w.y, acc[j].y);
        }
    }
    float* dst = sel ? g_xr : g_xl;
#pragma unroll
    for (int j = 0; j < 8; j++) {
        int n = nb + g * 8 + j;
        if (n < NN) {
            float2 lo = unpack2(acc[j].x), hi = unpack2(acc[j].y);
            *(float4*)&dst[(size_t)n * C1 + c0] = make_float4(lo.x, lo.y, hi.x, hi.y);
        }
    }
}

// edge logits L1, CSR order: f32x2 with smem-duplicated ea splats
__global__ __launch_bounds__(256) void k_edge1(const float* __restrict__ ea,
                                               const float* __restrict__ We,
                                               const float* __restrict__ att) {
    extern __shared__ float sm[];
    float* s_we  = sm;                      // 28*256 = 7168 floats
    float* s_ea2 = sm + 7168;               // 32*28*2 = 1792 floats
    __shared__ int s_src[TE], s_dst[TE], s_eid[TE];
    int t  = threadIdx.x;
    int eb = blockIdx.x * TE;
    if (t < TE) {
        s_src[t] = g_esrc[eb + t];
        s_dst[t] = g_edst[eb + t];
        s_eid[t] = g_eid[eb + t];
    }
    for (int i = t; i < ED * C1 / 4; i += 256)
        ((float4*)s_we)[i] = ((const float4*)We)[i];
    __syncthreads();
    for (int i = t; i < TE * ED; i += 256) {
        int e = i / ED, k = i - e * ED;
        float v = ea[(size_t)s_eid[e] * ED + k];
        s_ea2[i * 2] = v; s_ea2[i * 2 + 1] = v;
    }
    int cg = t & 63, eq = t >> 6;
    int c0 = cg * 4;
    ulonglong2 acc[8];
#pragma unroll
    for (int j = 0; j < 8; j++) {
        int e = eq * 8 + j;
        float4 a = *(const float4*)&g_xl[(size_t)s_src[e] * C1 + c0];
        float4 b = *(const float4*)&g_xr[(size_t)s_dst[e] * C1 + c0];
        acc[j].x = pack2(a.x + b.x, a.y + b.y);
        acc[j].y = pack2(a.z + b.z, a.w + b.w);
    }
    __syncthreads();
#pragma unroll 4
    for (int k = 0; k < ED; k++) {
        ulonglong2 w = *(const ulonglong2*)&s_we[k * C1 + c0];
#pragma unroll
        for (int j = 0; j < 8; j++) {
            unsigned long long e2 =
                *(const unsigned long long*)&s_ea2[((eq * 8 + j) * ED + k) * 2];
            acc[j].x = fma2(e2, w.x, acc[j].x);
            acc[j].y = fma2(e2, w.y, acc[j].y);
        }
    }
    float a0 = att[c0], a1 = att[c0 + 1], a2 = att[c0 + 2], a3 = att[c0 + 3];
    float part[8];
#pragma unroll
    for (int j = 0; j < 8; j++) {
        float2 lo = unpack2(acc[j].x), hi = unpack2(acc[j].y);
        part[j] = lrelu(lo.x) * a0 + lrelu(lo.y) * a1 +
                  lrelu(hi.x) * a2 + lrelu(hi.y) * a3;
    }
#pragma unroll
    for (int off = 8; off; off >>= 1) {
#pragma unroll
        for (int j = 0; j < 8; j++)
            part[j] += __shfl_down_sync(0xffffffffu, part[j], off);
    }
    int lane = t & 31;
    if ((lane & 15) == 0) {
        int h = cg >> 4;
#pragma unroll
        for (int j = 0; j < 8; j++) {
            int e = eq * 8 + j;
            g_logit[(size_t)(eb + e) * 4 + h] = part[j];   // CSR order
            atomicMaxF(&g_max[s_dst[e] * 4 + h], part[j]);
        }
    }
}

// aggregation L1 with fused softmax + fused LN stats
__global__ __launch_bounds__(256) void k_agg1(const float* __restrict__ bias) {
    int t = threadIdx.x;
    int n = blockIdx.x * 4 + (t >> 6);
    int t64 = t & 63;
    int lane = t & 31;
    int c0 = t64 * 4;
    int h  = t64 >> 4;
    int s = g_off[n], en = g_off[n + 1];
    float mx = g_max[n * 4 + h];
    float den = 0.f;
    float4 acc = make_float4(0.f, 0.f, 0.f, 0.f);
    for (int p = s; p < en; p++) {
        float ex = 0.f;
        if ((lane & 15) == 0) ex = expf(g_logit[(size_t)p * 4 + h] - mx);
        ex = __shfl_sync(0xffffffffu, ex, lane & 16);
        den += ex;
        int src = g_esrc[p];
        float4 v = *(const float4*)&g_xl[(size_t)src * C1 + c0];
        acc.x += ex * v.x; acc.y += ex * v.y;
        acc.z += ex * v.z; acc.w += ex * v.w;
    }
    float inv = 1.f / (den + 1e-16f);
    float4 bv = *(const float4*)&bias[c0];
    float4 o;
    o.x = acc.x * inv + bv.x; o.y = acc.y * inv + bv.y;
    o.z = acc.z * inv + bv.z; o.w = acc.w * inv + bv.w;
    *(float4*)&g_h1[(size_t)n * C1 + c0] = o;
    float sv = o.x + o.y + o.z + o.w;
    float qv = o.x * o.x + o.y * o.y + o.z * o.z + o.w * o.w;
#pragma unroll
    for (int off = 16; off; off >>= 1) {
        sv += __shfl_down_sync(0xffffffffu, sv, off);
        qv += __shfl_down_sync(0xffffffffu, qv, off);
    }
    __shared__ double sh[8], qh[8];
    int w = t >> 5;
    if (lane == 0) { sh[w] = (double)sv; qh[w] = (double)qv; }
    __syncthreads();
    if (t == 0) {
        double S = 0.0, Q = 0.0;
        for (int i = 0; i < 8; i++) { S += sh[i]; Q += qh[i]; }
        atomicAdd(&g_red[0], S); atomicAdd(&g_red[1], Q);
    }
}

// node transform L2: fused LN1+ReLU, duplicated-h smem, f32x2, w pairs via LDG.64
__global__ __launch_bounds__(256) void k_node2(const float* __restrict__ Wl,
                                               const float* __restrict__ bl,
                                               const float* __restrict__ Wr,
                                               const float* __restrict__ br,
                                               const float* __restrict__ lnw,
                                               const float* __restrict__ lnb) {
    __shared__ float hs2[16 * C1 * 2];      // 32 KB duplicated
    __shared__ float s_lnw[C1], s_lnb[C1];
    __shared__ float s_mf[2];
    int t = threadIdx.x;
    int nb = blockIdx.x * 16;
    if (t < C1) { s_lnw[t] = lnw[t]; s_lnb[t] = lnb[t]; }
    if (t == 0) {
        double M = (double)NN * C1;
        double mean = g_red[0] / M;
        double var  = g_red[1] / M - mean * mean;
        s_mf[0] = (float)mean;
        s_mf[1] = 1.f / ((float)sqrt(var > 0.0 ? var : 0.0) + 1e-5f);
    }
    __syncthreads();
    float mean = s_mf[0], f = s_mf[1];
    for (int i = t; i < 16 * C1 / 4; i += 256) {
        float4 v = *(const float4*)&g_h1[(size_t)nb * C1 + (size_t)i * 4];
        int k = (i & 63) * 4;
        float4 w4 = *(const float4*)&s_lnw[k];
        float4 b4 = *(const float4*)&s_lnb[k];
        v.x = (v.x - mean) * f * w4.x + b4.x; v.x = v.x > 0.f ? v.x : 0.f;
        v.y = (v.y - mean) * f * w4.y + b4.y; v.y = v.y > 0.f ? v.y : 0.f;
        v.z = (v.z - mean) * f * w4.z + b4.z; v.z = v.z > 0.f ? v.z : 0.f;
        v.w = (v.w - mean) * f * w4.w + b4.w; v.w = v.w > 0.f ? v.w : 0.f;
        *(float4*)&hs2[i * 8]     = make_float4(v.x, v.x, v.y, v.y);
        *(float4*)&hs2[i * 8 + 4] = make_float4(v.z, v.z, v.w, v.w);
    }
    __syncthreads();
    int cp = t & 31;           // col pair
    int c2 = cp * 2;
    int grp = t >> 5;          // 8 groups x 2 nodes
    int n0 = grp * 2, n1 = grp * 2 + 1;
    bool act = (c2 + 1) < C2;
    unsigned long long blv = 0, brv = 0;
    if (act) {
        blv = pack2(bl[c2], bl[c2 + 1]);
        brv = pack2(br[c2], br[c2 + 1]);
    }
    unsigned long long al0 = blv, al1 = blv, ar0 = brv, ar1 = brv;
#pragma unroll 4
    for (int k = 0; k < C1; k++) {
        unsigned long long wl = 0, wr = 0;
        if (act) {
            wl = *(const unsigned long long*)&Wl[k * C2 + c2];
            wr = *(const unsigned long long*)&Wr[k * C2 + c2];
        }
        unsigned long long h0 = *(const unsigned long long*)&hs2[(n0 * C1 + k) * 2];
        unsigned long long h1 = *(const unsigned long long*)&hs2[(n1 * C1 + k) * 2];
        al0 = fma2(h0, wl, al0);
        al1 = fma2(h1, wl, al1);
        ar0 = fma2(h0, wr, ar0);
        ar1 = fma2(h1, wr, ar1);
    }
    if (act) {
        float2 v;
        v = unpack2(al0); *(float2*)&g_xl[(size_t)(nb + n0) * C2 + c2] = v;
        v = unpack2(al1); *(float2*)&g_xl[(size_t)(nb + n1) * C2 + c2] = v;
        v = unpack2(ar0); *(float2*)&g_xr[(size_t)(nb + n0) * C2 + c2] = v;
        v = unpack2(ar1); *(float2*)&g_xr[(size_t)(nb + n1) * C2 + c2] = v;
    }
}

// edge logits L2 in CSR order, warp per edge
__global__ __launch_bounds__(256) void k_edge2(const float* __restrict__ ea,
                                               const float* __restrict__ We,
                                               const float* __restrict__ att) {
    int lane = threadIdx.x & 31;
    int gw = (blockIdx.x * blockDim.x + threadIdx.x) >> 5;
    int nw = (gridDim.x * blockDim.x) >> 5;
    int c0 = lane * 2;
    bool act = c0 < C2;
    float2 w[ED];
#pragma unroll
    for (int k = 0; k < ED; k++)
        w[k] = act ? *(const float2*)&We[k * C2 + c0] : make_float2(0.f, 0.f);
    float2 a2 = act ? *(const float2*)&att[c0] : make_float2(0.f, 0.f);
    for (int p = gw; p < EE; p += nw) {
        int src = g_esrc[p], dst = g_edst[p], e = g_eid[p];
        float eav = (lane < ED) ? ea[(size_t)e * ED + lane] : 0.f;
        float mx = 0.f, my = 0.f;
        if (act) {
            float2 u = *(const float2*)&g_xl[(size_t)src * C2 + c0];
            float2 v = *(const float2*)&g_xr[(size_t)dst * C2 + c0];
            mx = u.x + v.x; my = u.y + v.y;
        }
#pragma unroll
        for (int k = 0; k < ED; k++) {
            float a = __shfl_sync(0xffffffffu, eav, k);
            mx += a * w[k].x; my += a * w[k].y;
        }
        float pt = lrelu(mx) * a2.x + lrelu(my) * a2.y;
#pragma unroll
        for (int off = 16; off; off >>= 1) pt += __shfl_down_sync(0xffffffffu, pt, off);
        if (lane == 0) {
            g_logit[p] = pt;
            atomicMaxF(&g_max[4 * NN + dst], pt);
        }
    }
}

// aggregation L2 with fused softmax + fused LN stats
__global__ __launch_bounds__(256) void k_agg2(const float* __restrict__ bias) {
    int t = threadIdx.x;
    int n = blockIdx.x * 4 + (t >> 6);
    int t64 = t & 63;
    int lane = t & 31;
    int s = g_off[n], en = g_off[n + 1];
    bool act = t64 < C2;
    float mx = g_max[4 * NN + n];
    float den = 0.f, acc = 0.f;
    for (int p = s; p < en; p++) {
        float ex = 0.f;
        if (lane == 0) ex = expf(g_logit[p] - mx);
        ex = __shfl_sync(0xffffffffu, ex, 0);
        den += ex;
        int src = g_esrc[p];
        if (act) acc += ex * g_xl[(size_t)src * C2 + t64];
    }
    float o = 0.f;
    if (act) {
        o = acc / (den + 1e-16f) + bias[t64];
        g_o2[(size_t)n * C2 + t64] = o;
    }
    float sv = o, qv = o * o;
#pragma unroll
    for (int off = 16; off; off >>= 1) {
        sv += __shfl_down_sync(0xffffffffu, sv, off);
        qv += __shfl_down_sync(0xffffffffu, qv, off);
    }
    __shared__ double sh[8], qh[8];
    int w = t >> 5;
    if (lane == 0) { sh[w] = (double)sv; qh[w] = (double)qv; }
    __syncthreads();
    if (t == 0) {
        double S = 0.0, Q = 0.0;
        for (int i = 0; i < 8; i++) { S += sh[i]; Q += qh[i]; }
        atomicAdd(&g_red[2], S); atomicAdd(&g_red[3], Q);
    }
}

__global__ void k_ln2(float* __restrict__ out, const float* __restrict__ w,
                      const float* __restrict__ b) {
    int i = blockIdx.x * blockDim.x + threadIdx.x;
    if (i < NN * C2) {
        double M = (double)NN * C2;
        double mean = g_red[2] / M;
        double var  = g_red[3] / M - mean * mean;
        float f = 1.f / ((float)sqrt(var > 0.0 ? var : 0.0) + 1e-5f);
        int c = i % C2;
        out[i] = (g_o2[i] - (float)mean) * f * w[c] + b[c];
    }
}

extern "C" void kernel_launch(void* const* d_in, const int* in_sizes, int n_in,
                              void* d_out, int out_size) {
    const int*   x    = (const int*)d_in[0];
    const int*   ei   = (const int*)d_in[1];
    const float* ea   = (const float*)d_in[2];
    const float* emb  = (const float*)d_in[3];
    const float* Wl1  = (const float*)d_in[4];
    const float* bl1  = (const float*)d_in[5];
    const float* Wr1  = (const float*)d_in[6];
    const float* br1  = (const float*)d_in[7];
    const float* We1  = (const float*)d_in[8];
    const float* att1 = (const float*)d_in[9];
    const float* bias1= (const float*)d_in[10];
    const float* ln1w = (const float*)d_in[11];
    const float* ln1b = (const float*)d_in[12];
    const float* Wl2  = (const float*)d_in[13];
    const float* bl2  = (const float*)d_in[14];
    const float* Wr2  = (const float*)d_in[15];
    const float* br2  = (const float*)d_in[16];
    const float* We2  = (const float*)d_in[17];
    const float* att2 = (const float*)d_in[18];
    const float* bias2= (const float*)d_in[19];
    const float* ln2w = (const float*)d_in[20];
    const float* ln2b = (const float*)d_in[21];
    float* out = (float*)d_out;

    const int node1_smem = (EMBP * C1 + 32 * EMBP * 2) * 4;   // ~66.6 KB
    const int edge1_smem = (7168 + 1792) * 4;                 // ~35.8 KB
    const int scan_smem  = NN * 4;                            // 200 KB
    cudaFuncSetAttribute(k_node1, cudaFuncAttributeMaxDynamicSharedMemorySize, node1_smem);
    cudaFuncSetAttribute(k_edge1, cudaFuncAttributeMaxDynamicSharedMemorySize, edge1_smem);
    cudaFuncSetAttribute(k_scan,  cudaFuncAttributeMaxDynamicSharedMemorySize, scan_smem);

    k_init<<<(5 * NN + 255) / 256, 256>>>();                               // 1
    k_deg<<<(EE + 255) / 256, 256>>>(ei);                                  // 2
    k_scan<<<1, 1024, scan_smem>>>();                                      // 3
    k_node1<<<(NN + 31) / 32, 256, node1_smem>>>(x, emb, Wl1, bl1, 0);     // 4 <- profiled
    k_node1<<<(NN + 31) / 32, 256, node1_smem>>>(x, emb, Wr1, br1, 1);     // 5
    k_fill<<<(EE + 255) / 256, 256>>>(ei);                                 // 6
    k_edge1<<<EE / TE, 256, edge1_smem>>>(ea, We1, att1);                  // 7
    k_agg1<<<NN / 4, 256>>>(bias1);                                        // 8
    k_node2<<<NN / 16, 256>>>(Wl2, bl2, Wr2, br2, ln1w, ln1b);             // 9
    k_edge2<<<4096, 256>>>(ea, We2, att2);                                 // 10
    k_agg2<<<NN / 4, 256>>>(bias2);                                        // 11
    k_ln2<<<(NN * C2 + 255) / 256, 256>>>(out, ln2w, ln2b);                // 12
}